// round 1
// baseline (speedup 1.0000x reference)
#include <cuda_runtime.h>
#include <cstdint>

#define NL 10
#define AFFINE_EPS 1e-4f
#define LOG2PI 1.8378770664093453f

__device__ __forceinline__ float frcp(float x) {
    float r;
    asm("rcp.approx.f32 %0, %1;" : "=f"(r) : "f"(x));
    return r;
}

__global__ __launch_bounds__(256, 4) void flow_kernel(
    const float* __restrict__ x,
    const float* __restrict__ aff,
    const float* __restrict__ Ws,
    const float* __restrict__ bs,
    const float* __restrict__ lW,
    const float* __restrict__ lb,
    float* __restrict__ z_out,
    float* __restrict__ ld_out,
    int n)
{
    // 11 layers x 12 floats: [W0..W8, b0..b2], 48B per layer (16B aligned)
    __shared__ __align__(16) float sWB[(NL + 1) * 12];
    __shared__ float sConst;

    int tid = threadIdx.x;

    // Stage weights into shared (cooperative, one-time per block)
    if (tid < (NL + 1) * 12) {
        int layer = tid / 12, j = tid % 12;
        float val;
        if (layer < NL) val = (j < 9) ? Ws[layer * 9 + j] : bs[layer * 3 + (j - 9)];
        else            val = (j < 9) ? lW[j]             : lb[j - 9];
        sWB[tid] = val;
    }
    // One thread computes the row-independent sum of log|det W|
    if (tid == 255) {
        float c = 0.0f;
        #pragma unroll
        for (int i = 0; i <= NL; i++) {
            const float* W = (i < NL) ? (Ws + 9 * i) : lW;
            float det = W[0] * (W[4] * W[8] - W[5] * W[7])
                      - W[1] * (W[3] * W[8] - W[5] * W[6])
                      + W[2] * (W[3] * W[7] - W[4] * W[6]);
            c += __logf(fabsf(det));
        }
        sConst = c;
    }
    __syncthreads();

    int r = blockIdx.x * blockDim.x + tid;
    if (r >= n) return;

    // Load the full 240B affine row up-front (15 x float4, max MLP)
    float v[60];
    const float4* A = (const float4*)(aff + (size_t)r * 60);
    #pragma unroll
    for (int m = 0; m < 15; m++) {
        float4 t = A[m];
        v[4 * m + 0] = t.x; v[4 * m + 1] = t.y;
        v[4 * m + 2] = t.z; v[4 * m + 3] = t.w;
    }

    float z0 = x[3 * r + 0];
    float z1 = x[3 * r + 1];
    float z2 = x[3 * r + 2];

    float prod = 1.0f;   // running product of all 30 scales -> single log at end

    #pragma unroll
    for (int i = 0; i < NL; i++) {
        const float4* L = (const float4*)(sWB + 12 * i);
        float4 p0 = L[0], p1 = L[1], p2 = L[2];
        // W row-major: p0 = W[0..3], p1 = W[4..7], p2.x = W[8], p2.yzw = b

        float y0 = fmaf(z0, p0.x, fmaf(z1, p0.w, fmaf(z2, p1.z, p2.y)));
        float y1 = fmaf(z0, p0.y, fmaf(z1, p1.x, fmaf(z2, p1.w, p2.z)));
        float y2 = fmaf(z0, p0.z, fmaf(z1, p1.y, fmaf(z2, p2.x, p2.w)));

        float e0 = __expf(-(v[6 * i + 0] + 2.0f));
        float e1 = __expf(-(v[6 * i + 1] + 2.0f));
        float e2 = __expf(-(v[6 * i + 2] + 2.0f));
        float d0 = 1.0f + e0, d1 = 1.0f + e1, d2 = 1.0f + e2;

        // one rcp serves three reciprocals: 1/d_j = (prod of others) * rcp(d0*d1*d2)
        float rr = frcp(d0 * (d1 * d2));
        float s0 = fmaf(d1 * d2, rr, AFFINE_EPS);
        float s1 = fmaf(d0 * d2, rr, AFFINE_EPS);
        float s2 = fmaf(d0 * d1, rr, AFFINE_EPS);

        prod *= (s0 * s1) * s2;

        z0 = fmaf(y0, s0, v[6 * i + 3]);
        z1 = fmaf(y1, s1, v[6 * i + 4]);
        z2 = fmaf(y2, s2, v[6 * i + 5]);
    }

    // last linear layer
    {
        const float4* L = (const float4*)(sWB + 12 * NL);
        float4 p0 = L[0], p1 = L[1], p2 = L[2];
        float y0 = fmaf(z0, p0.x, fmaf(z1, p0.w, fmaf(z2, p1.z, p2.y)));
        float y1 = fmaf(z0, p0.y, fmaf(z1, p1.x, fmaf(z2, p1.w, p2.z)));
        float y2 = fmaf(z0, p0.z, fmaf(z1, p1.y, fmaf(z2, p2.x, p2.w)));
        z0 = y0; z1 = y1; z2 = y2;
    }

    float logdet = sConst + __logf(prod)
                 - 0.5f * (fmaf(z0, z0, fmaf(z1, z1, z2 * z2)))
                 - 1.5f * LOG2PI;

    z_out[3 * r + 0] = z0;
    z_out[3 * r + 1] = z1;
    z_out[3 * r + 2] = z2;
    ld_out[r] = logdet;
}

extern "C" void kernel_launch(void* const* d_in, const int* in_sizes, int n_in,
                              void* d_out, int out_size) {
    const float* x   = (const float*)d_in[0];
    const float* aff = (const float*)d_in[1];
    const float* Ws  = (const float*)d_in[2];
    const float* bs  = (const float*)d_in[3];
    const float* lW  = (const float*)d_in[4];
    const float* lb  = (const float*)d_in[5];

    int n = in_sizes[0] / 3;                 // N rows
    float* z_out  = (float*)d_out;           // [N, 3]
    float* ld_out = (float*)d_out + (size_t)3 * n;  // [N]

    int block = 256;
    int grid  = (n + block - 1) / block;
    flow_kernel<<<grid, block>>>(x, aff, Ws, bs, lW, lb, z_out, ld_out, n);
}

// round 2
// speedup vs baseline: 1.0897x; 1.0897x over previous
#include <cuda_runtime.h>
#include <cstdint>

#define NL 10
#define ROWS 128
#define AFFINE_EPS 1e-4f
#define LOG2PI 1.8378770664093453f

__device__ __forceinline__ float frcp(float x) {
    float r;
    asm("rcp.approx.f32 %0, %1;" : "=f"(r) : "f"(x));
    return r;
}

__global__ __launch_bounds__(ROWS, 8) void flow_kernel(
    const float* __restrict__ x,
    const float* __restrict__ aff,
    const float* __restrict__ Ws,
    const float* __restrict__ bs,
    const float* __restrict__ lW,
    const float* __restrict__ lb,
    float* __restrict__ z_out,
    float* __restrict__ ld_out,
    int n)
{
    // Coalesced staging tile for affine_info: 128 rows x 60 floats = 30720 B
    __shared__ __align__(16) float sA[ROWS * 60];
    // 11 layers x 12 floats: [W0..W8, b0..b2], 48B per layer (16B aligned)
    __shared__ __align__(16) float sWB[(NL + 1) * 12];
    __shared__ float sConst;

    int tid = threadIdx.x;

    // Stage weights into shared (cooperative)
    for (int i = tid; i < (NL + 1) * 12; i += ROWS) {
        int layer = i / 12, j = i % 12;
        float val;
        if (layer < NL) val = (j < 9) ? Ws[layer * 9 + j] : bs[layer * 3 + (j - 9)];
        else            val = (j < 9) ? lW[j]             : lb[j - 9];
        sWB[i] = val;
    }
    // One thread computes the row-independent sum of log|det W|
    if (tid == 0) {
        float c = 0.0f;
        #pragma unroll
        for (int i = 0; i <= NL; i++) {
            const float* W = (i < NL) ? (Ws + 9 * i) : lW;
            float det = W[0] * (W[4] * W[8] - W[5] * W[7])
                      - W[1] * (W[3] * W[8] - W[5] * W[6])
                      + W[2] * (W[3] * W[7] - W[4] * W[6]);
            c += __logf(fabsf(det));
        }
        sConst = c;
    }

    size_t rowbase = (size_t)blockIdx.x * ROWS;
    int r = (int)rowbase + tid;

    // --- Coalesced aff staging: global -> smem via cp.async.cg (L1 bypass) ---
    bool full = (rowbase + ROWS <= (size_t)n);
    if (full) {
        unsigned sbase = (unsigned)__cvta_generic_to_shared(sA);
        const char* g = (const char*)(aff + rowbase * 60);
        #pragma unroll
        for (int m = 0; m < 15; m++) {
            unsigned dst = sbase + (unsigned)(tid + ROWS * m) * 16u;
            const char* src = g + (size_t)(tid + ROWS * m) * 16u;
            asm volatile("cp.async.cg.shared.global [%0], [%1], 16;\n"
                         :: "r"(dst), "l"(src));
        }
        asm volatile("cp.async.commit_group;\n");
    } else if (r < n) {
        // tail block: per-thread copy of own row
        const float4* A = (const float4*)(aff + (size_t)r * 60);
        float4* S = (float4*)(sA + tid * 60);
        #pragma unroll
        for (int m = 0; m < 15; m++) S[m] = A[m];
    }

    // Overlap: issue x loads while cp.async is in flight
    float z0 = 0.f, z1 = 0.f, z2 = 0.f;
    if (r < n) {
        z0 = x[3 * r + 0];
        z1 = x[3 * r + 1];
        z2 = x[3 * r + 2];
    }

    if (full) asm volatile("cp.async.wait_group 0;\n");
    __syncthreads();

    if (r >= n) return;

    // Read own row from smem: 15 x LDS.128, conflict-free (unit idx 15t+m)
    float v[60];
    const float4* S = (const float4*)(sA + tid * 60);
    #pragma unroll
    for (int m = 0; m < 15; m++) {
        float4 t = S[m];
        v[4 * m + 0] = t.x; v[4 * m + 1] = t.y;
        v[4 * m + 2] = t.z; v[4 * m + 3] = t.w;
    }

    float prod = 1.0f;   // running product of all 30 scales -> single log at end

    #pragma unroll
    for (int i = 0; i < NL; i++) {
        const float4* L = (const float4*)(sWB + 12 * i);
        float4 p0 = L[0], p1 = L[1], p2 = L[2];
        // W row-major: p0 = W[0..3], p1 = W[4..7], p2.x = W[8], p2.yzw = b

        float y0 = fmaf(z0, p0.x, fmaf(z1, p0.w, fmaf(z2, p1.z, p2.y)));
        float y1 = fmaf(z0, p0.y, fmaf(z1, p1.x, fmaf(z2, p1.w, p2.z)));
        float y2 = fmaf(z0, p0.z, fmaf(z1, p1.y, fmaf(z2, p2.x, p2.w)));

        float e0 = __expf(-(v[6 * i + 0] + 2.0f));
        float e1 = __expf(-(v[6 * i + 1] + 2.0f));
        float e2 = __expf(-(v[6 * i + 2] + 2.0f));
        float d0 = 1.0f + e0, d1 = 1.0f + e1, d2 = 1.0f + e2;

        // one rcp serves three reciprocals: 1/d_j = (prod of others) * rcp(d0*d1*d2)
        float rr = frcp(d0 * (d1 * d2));
        float s0 = fmaf(d1 * d2, rr, AFFINE_EPS);
        float s1 = fmaf(d0 * d2, rr, AFFINE_EPS);
        float s2 = fmaf(d0 * d1, rr, AFFINE_EPS);

        prod *= (s0 * s1) * s2;

        z0 = fmaf(y0, s0, v[6 * i + 3]);
        z1 = fmaf(y1, s1, v[6 * i + 4]);
        z2 = fmaf(y2, s2, v[6 * i + 5]);
    }

    // last linear layer
    {
        const float4* L = (const float4*)(sWB + 12 * NL);
        float4 p0 = L[0], p1 = L[1], p2 = L[2];
        float y0 = fmaf(z0, p0.x, fmaf(z1, p0.w, fmaf(z2, p1.z, p2.y)));
        float y1 = fmaf(z0, p0.y, fmaf(z1, p1.x, fmaf(z2, p1.w, p2.z)));
        float y2 = fmaf(z0, p0.z, fmaf(z1, p1.y, fmaf(z2, p2.x, p2.w)));
        z0 = y0; z1 = y1; z2 = y2;
    }

    float logdet = sConst + __logf(prod)
                 - 0.5f * (fmaf(z0, z0, fmaf(z1, z1, z2 * z2)))
                 - 1.5f * LOG2PI;

    z_out[3 * r + 0] = z0;
    z_out[3 * r + 1] = z1;
    z_out[3 * r + 2] = z2;
    ld_out[r] = logdet;
}

extern "C" void kernel_launch(void* const* d_in, const int* in_sizes, int n_in,
                              void* d_out, int out_size) {
    const float* x   = (const float*)d_in[0];
    const float* aff = (const float*)d_in[1];
    const float* Ws  = (const float*)d_in[2];
    const float* bs  = (const float*)d_in[3];
    const float* lW  = (const float*)d_in[4];
    const float* lb  = (const float*)d_in[5];

    int n = in_sizes[0] / 3;                 // N rows
    float* z_out  = (float*)d_out;           // [N, 3]
    float* ld_out = (float*)d_out + (size_t)3 * n;  // [N]

    int grid = (n + ROWS - 1) / ROWS;
    flow_kernel<<<grid, ROWS>>>(x, aff, Ws, bs, lW, lb, z_out, ld_out, n);
}